// round 16
// baseline (speedup 1.0000x reference)
#include <cuda_runtime.h>
#include <cuda_fp16.h>
#include <math.h>
#include <stdint.h>

// Problem constants
#define BB 2
#define SS 2048
#define DD 1024
#define HH 16
#define DKK 64
#define DFFN 4096
#define NTOK (BB*SS)          // 4096
#define LN_EPS 1e-6f

typedef __half h16;

// ---------------------------------------------------------------------------
// Scratch (static __device__ arrays: allocation-guard-safe)
// ---------------------------------------------------------------------------
__device__ h16   g_xn  [(size_t)NTOK*DD];
__device__ h16   g_qb  [(size_t)NTOK*DD];
__device__ h16   g_kb  [(size_t)NTOK*DD];
__device__ h16   g_vb  [(size_t)NTOK*DD];
__device__ h16   g_av  [(size_t)NTOK*DD];
__device__ float g_x1  [(size_t)NTOK*DD];
__device__ h16   g_xn2 [(size_t)NTOK*DD];
__device__ h16   g_hb  [(size_t)NTOK*DFFN];
__device__ h16   g_wqh [(size_t)DD*DD];
__device__ h16   g_wkh [(size_t)DD*DD];
__device__ h16   g_wvh [(size_t)DD*DD];
__device__ h16   g_woh [(size_t)DD*DD];
__device__ h16   g_w1h [(size_t)DFFN*DD];
__device__ h16   g_w2h [(size_t)DD*DFFN];

// ---------------------------------------------------------------------------
// PTX helpers (cp.async + mma.sync + ldmatrix + ex2)
// ---------------------------------------------------------------------------
__device__ __forceinline__ uint32_t smem_u32(const void* p) {
    uint32_t a;
    asm("{ .reg .u64 t; cvta.to.shared.u64 t, %1; cvt.u32.u64 %0, t; }"
        : "=r"(a) : "l"(p));
    return a;
}
__device__ __forceinline__ void cp16(uint32_t d, const void* s) {
    asm volatile("cp.async.cg.shared.global [%0], [%1], 16;\n" :: "r"(d), "l"(s));
}
__device__ __forceinline__ void cp_commit() { asm volatile("cp.async.commit_group;\n" ::); }
template<int N> __device__ __forceinline__ void cp_wait() {
    asm volatile("cp.async.wait_group %0;\n" :: "n"(N));
}

__device__ __forceinline__ void mma16816(float* c, const uint32_t* a, const uint32_t* b) {
    asm volatile(
        "mma.sync.aligned.m16n8k16.row.col.f32.f16.f16.f32 "
        "{%0,%1,%2,%3}, {%4,%5,%6,%7}, {%8,%9}, {%0,%1,%2,%3};"
        : "+f"(c[0]), "+f"(c[1]), "+f"(c[2]), "+f"(c[3])
        : "r"(a[0]), "r"(a[1]), "r"(a[2]), "r"(a[3]), "r"(b[0]), "r"(b[1]));
}
__device__ __forceinline__ void ldsm4(uint32_t* r, uint32_t addr) {
    asm volatile("ldmatrix.sync.aligned.m8n8.x4.shared.b16 {%0,%1,%2,%3}, [%4];"
        : "=r"(r[0]), "=r"(r[1]), "=r"(r[2]), "=r"(r[3]) : "r"(addr));
}
__device__ __forceinline__ void ldsm4t(uint32_t* r, uint32_t addr) {
    asm volatile("ldmatrix.sync.aligned.m8n8.x4.trans.shared.b16 {%0,%1,%2,%3}, [%4];"
        : "=r"(r[0]), "=r"(r[1]), "=r"(r[2]), "=r"(r[3]) : "r"(addr));
}
__device__ __forceinline__ uint32_t packh(float lo, float hi) {
    __half2 t = __floats2half2_rn(lo, hi);
    return *(uint32_t*)&t;
}
__device__ __forceinline__ float ex2(float x) {
    float y;
    asm("ex2.approx.ftz.f32 %0, %1;" : "=f"(y) : "f"(x));
    return y;
}

// ---------------------------------------------------------------------------
// Fused convert of all 6 weight matrices fp32 -> fp16, one launch.
// ---------------------------------------------------------------------------
#define CVT_Q (DD*DD/4)        // 262144 (= 2^18)
#define CVT_F (DFFN*DD/4)      // 1048576
#define CVT_TOTAL (4*CVT_Q + 2*CVT_F)   // 3145728

__global__ __launch_bounds__(256) void cvt_all(
    const float* __restrict__ wq, const float* __restrict__ wk,
    const float* __restrict__ wv, const float* __restrict__ wo,
    const float* __restrict__ w1, const float* __restrict__ w2,
    h16* __restrict__ oq, h16* __restrict__ ok, h16* __restrict__ ov,
    h16* __restrict__ oo, h16* __restrict__ o1, h16* __restrict__ o2)
{
    int i = blockIdx.x * 256 + threadIdx.x;
    if (i >= CVT_TOTAL) return;
    const float* src; h16* dst; int off;
    if (i < 4*CVT_Q) {
        int w = i >> 18; off = i & (CVT_Q - 1);
        src = (w==0) ? wq : (w==1) ? wk : (w==2) ? wv : wo;
        dst = (w==0) ? oq : (w==1) ? ok : (w==2) ? ov : oo;
    } else if (i < 4*CVT_Q + CVT_F) {
        src = w1; dst = o1; off = i - 4*CVT_Q;
    } else {
        src = w2; dst = o2; off = i - 4*CVT_Q - CVT_F;
    }
    float4 v = ((const float4*)src)[off];
    ((__half2*)dst)[off*2]   = __floats2half2_rn(v.x, v.y);
    ((__half2*)dst)[off*2+1] = __floats2half2_rn(v.z, v.w);
}

// ---------------------------------------------------------------------------
// LayerNorm -> fp16, warp-per-row. 8 rows per 256-thread CTA, no barriers.
// torch semantics: alpha * (x - mean) / (sqrt(var_unbiased) + eps) + bias
// ---------------------------------------------------------------------------
__global__ __launch_bounds__(256) void layernorm_k(
    const float* __restrict__ x, const float* __restrict__ alpha,
    const float* __restrict__ beta, h16* __restrict__ oh)
{
    int row = blockIdx.x * 8 + (threadIdx.x >> 5);
    int l = threadIdx.x & 31;
    const float4* xr = (const float4*)(x + (size_t)row * DD);

    float4 v[8];
    float s = 0.f, s2 = 0.f;
    #pragma unroll
    for (int j = 0; j < 8; j++) {
        v[j] = xr[l + j * 32];
        s  += v[j].x + v[j].y + v[j].z + v[j].w;
        s2 += v[j].x*v[j].x + v[j].y*v[j].y + v[j].z*v[j].z + v[j].w*v[j].w;
    }
    #pragma unroll
    for (int o = 16; o > 0; o >>= 1) {
        s  += __shfl_xor_sync(0xffffffffu, s,  o);
        s2 += __shfl_xor_sync(0xffffffffu, s2, o);
    }
    float mean = s * (1.0f / (float)DD);
    float var  = (s2 - (float)DD * mean * mean) * (1.0f / (float)(DD - 1));
    var = fmaxf(var, 0.0f);
    float inv = 1.0f / (sqrtf(var) + LN_EPS);

    const float4* ap = (const float4*)alpha;
    const float4* bp = (const float4*)beta;
    __half2* op = (__half2*)(oh + (size_t)row * DD);
    #pragma unroll
    for (int j = 0; j < 8; j++) {
        int idx = l + j * 32;
        float4 a = ap[idx], bb = bp[idx];
        float o0 = a.x * (v[j].x - mean) * inv + bb.x;
        float o1 = a.y * (v[j].y - mean) * inv + bb.y;
        float o2 = a.z * (v[j].z - mean) * inv + bb.z;
        float o3 = a.w * (v[j].w - mean) * inv + bb.w;
        op[idx * 2]     = __floats2half2_rn(o0, o1);
        op[idx * 2 + 1] = __floats2half2_rn(o2, o3);
    }
}

// ---------------------------------------------------------------------------
// GEMM tiling: 128x128 tile, BK=32, 256 threads (8 warps 4x2; 32x64/warp),
// single fp16 product, 5-stage cp.async pipeline (3 in flight), ONE sync
// per chunk. Smem 102400 B -> 2 CTAs/SM (204.8 KB of 228 KB).
// ---------------------------------------------------------------------------
#define BK 32
#define LDSX 40                       // padded row stride in h16 elems (80B)
#define MATB (128 * LDSX * 2)         // 10240 B per matrix tile
#define STAGE (2 * MATB)              // A, B
#define NSTG 5
#define GEMM_SMEM (NSTG * STAGE)      // 102400 B

__device__ __forceinline__ uint32_t a_ldsm_off(int lane) {
    int r = ((lane >> 3) & 1) * 8 + (lane & 7);
    int c = (lane >> 4) * 8;
    return (uint32_t)(r * LDSX + c) * 2;
}
__device__ __forceinline__ uint32_t b_ldsm_off(int lane) {
    int r = (lane >> 4) * 8 + (lane & 7);
    int c = ((lane >> 3) & 1) * 8;
    return (uint32_t)(r * LDSX + c) * 2;
}

template<bool BIAS, bool RELU, bool RES, bool OUTH>
__device__ __forceinline__ void gemm_body(
    const h16* __restrict__ A, const h16* __restrict__ B,
    const float* __restrict__ bias, const float* __restrict__ res,
    float* __restrict__ Cf, h16* __restrict__ Ch,
    int m0, int n0, int N, int K, uint32_t sbase)
{
    int tid = threadIdx.x, lane = tid & 31, wid = tid >> 5;
    int wm = wid & 3, wn = wid >> 2;
    int lr = lane >> 2, lk2 = (lane & 3) * 2;
    uint32_t aoff = a_ldsm_off(lane) + (uint32_t)(wm * 32) * (LDSX * 2);
    uint32_t boff = b_ldsm_off(lane) + (uint32_t)(wn * 64) * (LDSX * 2);

    float acc[2][8][4];
    #pragma unroll
    for (int a = 0; a < 2; a++)
        #pragma unroll
        for (int b = 0; b < 8; b++)
            #pragma unroll
            for (int c = 0; c < 4; c++) acc[a][b][c] = 0.f;

    const int NC = K / BK;

    auto load_chunk = [&](int c, int buf) {
        int kc = c * BK;
        uint32_t base = sbase + buf * STAGE;
        #pragma unroll
        for (int T = 0; T < 2; T++) {
            const h16* src = (T == 0) ? A : B;
            int r0 = (T == 0) ? m0 : n0;
            uint32_t mb = base + T * MATB;
            int row = tid >> 1, c16 = tid & 1;
            cp16(mb + row * (LDSX * 2) + c16 * 32,
                 src + (size_t)(r0 + row) * K + kc + c16 * 16);
            cp16(mb + row * (LDSX * 2) + c16 * 32 + 16,
                 src + (size_t)(r0 + row) * K + kc + c16 * 16 + 8);
        }
        cp_commit();
    };

    load_chunk(0, 0);
    load_chunk(1, 1);
    load_chunk(2, 2);
    load_chunk(3, 3);

    for (int c = 0; c < NC; c++) {
        // chunk c must be complete: keep at most 3 younger groups in flight
        if (c + 4 < NC) cp_wait<3>();
        else if (c + 3 < NC) cp_wait<2>();
        else if (c + 2 < NC) cp_wait<1>();
        else cp_wait<0>();
        __syncthreads();
        // Prefetch c+4 into slot (c+4)%5 == (c-1)%5; readers of that slot
        // (iter c-1) all passed the sync above.
        if (c + 4 < NC) load_chunk(c + 4, (c + 4) % NSTG);

        uint32_t stg = sbase + (c % NSTG) * STAGE;
        uint32_t sA = stg + aoff;
        uint32_t sB = stg + MATB + boff;

        #pragma unroll
        for (int ks = 0; ks < 2; ks++) {
            uint32_t ah[2][4];
            #pragma unroll
            for (int mf = 0; mf < 2; mf++)
                ldsm4(ah[mf], sA + (uint32_t)(mf * 16) * (LDSX * 2) + ks * 32);
            #pragma unroll
            for (int nf2 = 0; nf2 < 4; nf2++) {
                uint32_t bh[4];
                ldsm4(bh, sB + (uint32_t)(nf2 * 16) * (LDSX * 2) + ks * 32);
                #pragma unroll
                for (int mf = 0; mf < 2; mf++) {
                    mma16816(acc[mf][2*nf2],     ah[mf], bh);
                    mma16816(acc[mf][2*nf2 + 1], ah[mf], bh + 2);
                }
            }
        }
    }

    // epilogue
    #pragma unroll
    for (int mf = 0; mf < 2; mf++) {
        int r0 = m0 + wm * 32 + mf * 16 + lr;
        #pragma unroll
        for (int nf = 0; nf < 8; nf++) {
            int col = n0 + wn * 64 + nf * 8 + lk2;
            float* cc = acc[mf][nf];
            float v00 = cc[0], v01 = cc[1], v10 = cc[2], v11 = cc[3];
            if (BIAS) {
                float b0 = __ldg(bias + col), b1 = __ldg(bias + col + 1);
                v00 += b0; v01 += b1; v10 += b0; v11 += b1;
            }
            if (RELU) {
                v00 = fmaxf(v00, 0.f); v01 = fmaxf(v01, 0.f);
                v10 = fmaxf(v10, 0.f); v11 = fmaxf(v11, 0.f);
            }
            if (RES) {
                float2 ra = *(const float2*)(res + (size_t)r0 * N + col);
                float2 rb = *(const float2*)(res + (size_t)(r0 + 8) * N + col);
                v00 += ra.x; v01 += ra.y; v10 += rb.x; v11 += rb.y;
            }
            if (OUTH) {
                *(__half2*)(Ch + (size_t)r0 * N + col)       = __floats2half2_rn(v00, v01);
                *(__half2*)(Ch + (size_t)(r0 + 8) * N + col) = __floats2half2_rn(v10, v11);
            } else {
                *(float2*)(Cf + (size_t)r0 * N + col)       = make_float2(v00, v01);
                *(float2*)(Cf + (size_t)(r0 + 8) * N + col) = make_float2(v10, v11);
            }
        }
    }
}

template<bool BIAS, bool RELU, bool RES, bool OUTH>
__global__ __launch_bounds__(256, 2) void gemm_h(
    const h16* __restrict__ A, const h16* __restrict__ B,
    const float* __restrict__ bias, const float* __restrict__ res,
    float* __restrict__ Cf, h16* __restrict__ Ch, int N, int K)
{
    extern __shared__ char sm_raw[];
    gemm_body<BIAS, RELU, RES, OUTH>(
        A, B, bias, res, Cf, Ch,
        blockIdx.y * 128, blockIdx.x * 128, N, K, smem_u32(sm_raw));
}

// Fused QKV: grid.x = 24; which = bx>>3 selects weight/output.
__global__ __launch_bounds__(256, 2) void gemm_qkv(
    const h16* __restrict__ A,
    const h16* __restrict__ B0, const h16* __restrict__ B1,
    const h16* __restrict__ B2,
    h16* __restrict__ C0, h16* __restrict__ C1, h16* __restrict__ C2)
{
    extern __shared__ char sm_raw[];
    int which = blockIdx.x >> 3;
    const h16* Bw = (which == 0) ? B0 : (which == 1) ? B1 : B2;
    h16* Cw = (which == 0) ? C0 : (which == 1) ? C1 : C2;
    gemm_body<false, false, false, true>(
        A, Bw, nullptr, nullptr, nullptr, Cw,
        blockIdx.y * 128, (blockIdx.x & 7) * 128, DD, DD, smem_u32(sm_raw));
}

// ---------------------------------------------------------------------------
// Flash attention (fp16 mma.sync): one CTA per (b, h, 128-query tile).
// 8 warps x 16 Q rows. K/V chunks of 64 keys, 4-stage cp.async pipeline
// (2 in flight). Base-2 online softmax with Q-folded scale, raw ex2,
// warp-uniform rescale skip.
// ---------------------------------------------------------------------------
#define ANSTG 4
#define AKST 72                       // smem row stride in h16 (144 B)
#define AKBUF (64 * AKST * 2)         // 9216 B per K (or V) stage
#define AVS_OFF (ANSTG * AKBUF)       // 36864
#define AMSK_OFF (2 * ANSTG * AKBUF)  // 73728
#define ATTN_SMEM (AMSK_OFF + ANSTG * 64 * 4)   // 74752 B

#define QSCALE 0.18033688011112042f   // 0.125 * log2(e)

__global__ __launch_bounds__(256, 2) void fattn_k(
    const h16* __restrict__ qg, const h16* __restrict__ kg,
    const h16* __restrict__ vg, const int* __restrict__ mask,
    h16* __restrict__ avo)
{
    extern __shared__ char sm_raw[];
    uint32_t sbase = smem_u32(sm_raw);
    int* msk_s = (int*)(sm_raw + AMSK_OFF);

    int t = threadIdx.x, lane = t & 31, w = t >> 5;
    int h = blockIdx.y & (HH - 1), b = blockIdx.y >> 4;
    size_t base = (size_t)b * SS * DD + h * DKK;
    int q0 = blockIdx.x * 128 + w * 16;
    int lr = lane >> 2, q4 = lane & 3;
    int l7 = lane & 7, lg8 = (lane >> 3) & 1, lg16 = (lane >> 4) & 1;

    const __half2 qs2 = __float2half2_rn(QSCALE);
    uint32_t qf[4][4];
    #pragma unroll
    for (int ks = 0; ks < 4; ks++) {
        int col = ks * 16 + q4 * 2;
        uint32_t r0 = *(const uint32_t*)(qg + base + (size_t)(q0 + lr) * DD + col);
        uint32_t r1 = *(const uint32_t*)(qg + base + (size_t)(q0 + lr + 8) * DD + col);
        uint32_t r2 = *(const uint32_t*)(qg + base + (size_t)(q0 + lr) * DD + col + 8);
        uint32_t r3 = *(const uint32_t*)(qg + base + (size_t)(q0 + lr + 8) * DD + col + 8);
        __half2 h0 = __hmul2(*(__half2*)&r0, qs2);
        __half2 h1 = __hmul2(*(__half2*)&r1, qs2);
        __half2 h2 = __hmul2(*(__half2*)&r2, qs2);
        __half2 h3 = __hmul2(*(__half2*)&r3, qs2);
        qf[ks][0] = *(uint32_t*)&h0;
        qf[ks][1] = *(uint32_t*)&h1;
        qf[ks][2] = *(uint32_t*)&h2;
        qf[ks][3] = *(uint32_t*)&h3;
    }

    float vacc[8][4];
    #pragma unroll
    for (int nf = 0; nf < 8; nf++)
        #pragma unroll
        for (int c = 0; c < 4; c++) vacc[nf][c] = 0.f;
    float m0 = -1e30f, m1 = -1e30f, l0 = 0.f, l1 = 0.f;

    const int NC = SS / 64;

    auto load_chunk = [&](int c, int buf) {
        int key0 = c * 64;
        uint32_t kbAddr = sbase + buf * AKBUF;
        uint32_t vbAddr = sbase + AVS_OFF + buf * AKBUF;
        #pragma unroll
        for (int i = 0; i < 2; i++) {
            int idx = t * 2 + i;
            int row = idx >> 3, seg = idx & 7;
            cp16(kbAddr + row * (AKST * 2) + seg * 16,
                 kg + base + (size_t)(key0 + row) * DD + seg * 8);
            cp16(vbAddr + row * (AKST * 2) + seg * 16,
                 vg + base + (size_t)(key0 + row) * DD + seg * 8);
        }
        if (t < 16)
            cp16(sbase + AMSK_OFF + buf * 256 + t * 16,
                 mask + b * SS + key0 + t * 4);
        cp_commit();
    };

    load_chunk(0, 0);
    load_chunk(1, 1);
    load_chunk(2, 2);

    for (int c = 0; c < NC; c++) {
        if (c + 3 < NC) cp_wait<2>();
        else if (c + 2 < NC) cp_wait<1>();
        else cp_wait<0>();
        __syncthreads();
        // Prefetch c+3 into slot (c+3)%4 == (c-1)%4; readers passed the sync.
        if (c + 3 < NC) load_chunk(c + 3, (c + 3) % ANSTG);
        int buf = c % ANSTG;

        float sacc[8][4];
        #pragma unroll
        for (int nf = 0; nf < 8; nf++)
            #pragma unroll
            for (int cc = 0; cc < 4; cc++) sacc[nf][cc] = 0.f;

        uint32_t ksb = sbase + buf * AKBUF;
        #pragma unroll
        for (int ks = 0; ks < 4; ks++) {
            #pragma unroll
            for (int nfp = 0; nfp < 4; nfp++) {
                uint32_t kf[4];
                uint32_t addr = ksb
                    + (uint32_t)(nfp * 16 + lg16 * 8 + l7) * (AKST * 2)
                    + ks * 32 + lg8 * 16;
                ldsm4(kf, addr);
                mma16816(sacc[2*nfp],     qf[ks], kf);
                mma16816(sacc[2*nfp + 1], qf[ks], kf + 2);
            }
        }

        #pragma unroll
        for (int nf = 0; nf < 8; nf++) {
            int col = nf * 8 + q4 * 2;
            int mk0 = msk_s[buf * 64 + col], mk1 = msk_s[buf * 64 + col + 1];
            if (!mk0) { sacc[nf][0] = -3e8f; sacc[nf][2] = -3e8f; }
            if (!mk1) { sacc[nf][1] = -3e8f; sacc[nf][3] = -3e8f; }
        }

        float cm0 = -1e30f, cm1 = -1e30f;
        #pragma unroll
        for (int nf = 0; nf < 8; nf++) {
            cm0 = fmaxf(cm0, fmaxf(sacc[nf][0], sacc[nf][1]));
            cm1 = fmaxf(cm1, fmaxf(sacc[nf][2], sacc[nf][3]));
        }
        cm0 = fmaxf(cm0, __shfl_xor_sync(0xffffffffu, cm0, 1));
        cm0 = fmaxf(cm0, __shfl_xor_sync(0xffffffffu, cm0, 2));
        cm1 = fmaxf(cm1, __shfl_xor_sync(0xffffffffu, cm1, 1));
        cm1 = fmaxf(cm1, __shfl_xor_sync(0xffffffffu, cm1, 2));
        float nm0 = fmaxf(m0, cm0), nm1 = fmaxf(m1, cm1);

        bool stable = (nm0 == m0) && (nm1 == m1);
        if (!__all_sync(0xffffffffu, stable)) {
            float sc0 = ex2(m0 - nm0), sc1 = ex2(m1 - nm1);
            l0 *= sc0; l1 *= sc1;
            #pragma unroll
            for (int nf = 0; nf < 8; nf++) {
                vacc[nf][0] *= sc0; vacc[nf][1] *= sc0;
                vacc[nf][2] *= sc1; vacc[nf][3] *= sc1;
            }
            m0 = nm0; m1 = nm1;
        }

        #pragma unroll
        for (int nf = 0; nf < 8; nf++) {
            float p0 = ex2(sacc[nf][0] - m0);
            float p1 = ex2(sacc[nf][1] - m0);
            float p2 = ex2(sacc[nf][2] - m1);
            float p3 = ex2(sacc[nf][3] - m1);
            sacc[nf][0] = p0; sacc[nf][1] = p1;
            sacc[nf][2] = p2; sacc[nf][3] = p3;
            l0 += p0 + p1; l1 += p2 + p3;
        }

        uint32_t pf[4][4];
        #pragma unroll
        for (int ks = 0; ks < 4; ks++) {
            pf[ks][0] = packh(sacc[2*ks][0],     sacc[2*ks][1]);
            pf[ks][1] = packh(sacc[2*ks][2],     sacc[2*ks][3]);
            pf[ks][2] = packh(sacc[2*ks + 1][0], sacc[2*ks + 1][1]);
            pf[ks][3] = packh(sacc[2*ks + 1][2], sacc[2*ks + 1][3]);
        }

        uint32_t vsb = sbase + AVS_OFF + buf * AKBUF;
        #pragma unroll
        for (int nfp = 0; nfp < 4; nfp++) {
            #pragma unroll
            for (int ks = 0; ks < 4; ks++) {
                uint32_t vf[4];
                uint32_t addr = vsb
                    + (uint32_t)(ks * 16 + lg8 * 8 + l7) * (AKST * 2)
                    + nfp * 32 + lg16 * 16;
                ldsm4t(vf, addr);
                mma16816(vacc[2*nfp],     pf[ks], vf);
                mma16816(vacc[2*nfp + 1], pf[ks], vf + 2);
            }
        }
    }

    l0 += __shfl_xor_sync(0xffffffffu, l0, 1);
    l0 += __shfl_xor_sync(0xffffffffu, l0, 2);
    l1 += __shfl_xor_sync(0xffffffffu, l1, 1);
    l1 += __shfl_xor_sync(0xffffffffu, l1, 2);
    float r0 = 1.0f / l0, r1 = 1.0f / l1;

    #pragma unroll
    for (int nf = 0; nf < 8; nf++) {
        int col = nf * 8 + q4 * 2;
        size_t o0 = base + (size_t)(q0 + lr) * DD + col;
        size_t o1 = base + (size_t)(q0 + lr + 8) * DD + col;
        *(__half2*)(avo + o0) = __floats2half2_rn(vacc[nf][0] * r0, vacc[nf][1] * r0);
        *(__half2*)(avo + o1) = __floats2half2_rn(vacc[nf][2] * r1, vacc[nf][3] * r1);
    }
}

// ---------------------------------------------------------------------------
// Driver
// ---------------------------------------------------------------------------
extern "C" void kernel_launch(void* const* d_in, const int* in_sizes, int n_in,
                              void* d_out, int out_size)
{
    const float* x      = (const float*)d_in[0];
    const int*   mask   = (const int*)  d_in[1];
    const float* wq     = (const float*)d_in[2];
    const float* wk     = (const float*)d_in[3];
    const float* wv     = (const float*)d_in[4];
    const float* wo     = (const float*)d_in[5];
    const float* w1     = (const float*)d_in[6];
    const float* b1     = (const float*)d_in[7];
    const float* w2     = (const float*)d_in[8];
    const float* b2     = (const float*)d_in[9];
    const float* alpha1 = (const float*)d_in[10];
    const float* bias1  = (const float*)d_in[11];
    const float* alpha2 = (const float*)d_in[12];
    const float* bias2  = (const float*)d_in[13];
    float* out = (float*)d_out;

    h16 *xn, *qb, *kb, *vb, *av, *xn2, *hb;
    h16 *wqh, *wkh, *wvh, *woh, *w1h, *w2h;
    float *x1;
    cudaGetSymbolAddress((void**)&xn,   g_xn);
    cudaGetSymbolAddress((void**)&qb,   g_qb);   cudaGetSymbolAddress((void**)&kb,   g_kb);
    cudaGetSymbolAddress((void**)&vb,   g_vb);
    cudaGetSymbolAddress((void**)&av,   g_av);
    cudaGetSymbolAddress((void**)&x1,   g_x1);
    cudaGetSymbolAddress((void**)&xn2,  g_xn2);
    cudaGetSymbolAddress((void**)&hb,   g_hb);
    cudaGetSymbolAddress((void**)&wqh,  g_wqh);
    cudaGetSymbolAddress((void**)&wkh,  g_wkh);
    cudaGetSymbolAddress((void**)&wvh,  g_wvh);
    cudaGetSymbolAddress((void**)&woh,  g_woh);
    cudaGetSymbolAddress((void**)&w1h,  g_w1h);
    cudaGetSymbolAddress((void**)&w2h,  g_w2h);

    cudaFuncSetAttribute(gemm_h<false,false,true,false>,
                         cudaFuncAttributeMaxDynamicSharedMemorySize, GEMM_SMEM);
    cudaFuncSetAttribute(gemm_h<true,true,false,true>,
                         cudaFuncAttributeMaxDynamicSharedMemorySize, GEMM_SMEM);
    cudaFuncSetAttribute(gemm_h<true,false,true,false>,
                         cudaFuncAttributeMaxDynamicSharedMemorySize, GEMM_SMEM);
    cudaFuncSetAttribute(gemm_qkv,
                         cudaFuncAttributeMaxDynamicSharedMemorySize, GEMM_SMEM);
    cudaFuncSetAttribute(fattn_k,
                         cudaFuncAttributeMaxDynamicSharedMemorySize, ATTN_SMEM);

    // 0. all weights -> fp16, single launch
    cvt_all<<<(CVT_TOTAL + 255)/256, 256>>>(
        wq, wk, wv, wo, w1, w2, wqh, wkh, wvh, woh, w1h, w2h);

    // 1. LN1 -> fp16 (warp-per-row)
    layernorm_k<<<NTOK / 8, 256>>>(x, alpha1, bias1, xn);

    // 2. fused Q/K/V projections (fp16)
    dim3 gQKV(3 * (DD / 128), NTOK / 128);  // (24, 32)
    gemm_qkv<<<gQKV, 256, GEMM_SMEM>>>(xn, wqh, wkh, wvh, qb, kb, vb);

    // 3. flash attention -> fp16
    dim3 gAttn(SS / 128, BB * HH);          // (16, 32)
    fattn_k<<<gAttn, 256, ATTN_SMEM>>>(qb, kb, vb, mask, av);

    // 4. output projection + residual(x) -> x1 fp32
    dim3 gProj(DD / 128, NTOK / 128);       // (8, 32)
    gemm_h<false,false,true,false><<<gProj, 256, GEMM_SMEM>>>(
        av, woh, nullptr, x, x1, nullptr, DD, DD);

    // 5. LN2 -> fp16 (warp-per-row)
    layernorm_k<<<NTOK / 8, 256>>>(x1, alpha2, bias2, xn2);

    // 6. FFN up: relu(xn2@w1^T + b1) -> fp16
    dim3 gF1(DFFN / 128, NTOK / 128);       // (32, 32)
    gemm_h<true,true,false,true><<<gF1, 256, GEMM_SMEM>>>(
        xn2, w1h, b1, nullptr, nullptr, hb, DFFN, DD);

    // 7. FFN down: h@w2^T + b2 + x1 -> out fp32
    gemm_h<true,false,true,false><<<gProj, 256, GEMM_SMEM>>>(
        hb, w2h, b2, x1, out, nullptr, DD, DFFN);
}

// round 17
// speedup vs baseline: 1.0271x; 1.0271x over previous
#include <cuda_runtime.h>
#include <cuda_fp16.h>
#include <math.h>
#include <stdint.h>

// Problem constants
#define BB 2
#define SS 2048
#define DD 1024
#define HH 16
#define DKK 64
#define DFFN 4096
#define NTOK (BB*SS)          // 4096
#define LN_EPS 1e-6f

typedef __half h16;

// ---------------------------------------------------------------------------
// Scratch (static __device__ arrays: allocation-guard-safe)
// ---------------------------------------------------------------------------
__device__ h16   g_xn  [(size_t)NTOK*DD];
__device__ h16   g_qb  [(size_t)NTOK*DD];
__device__ h16   g_kb  [(size_t)NTOK*DD];
__device__ h16   g_vb  [(size_t)NTOK*DD];
__device__ h16   g_av  [(size_t)NTOK*DD];
__device__ float g_x1  [(size_t)NTOK*DD];
__device__ h16   g_xn2 [(size_t)NTOK*DD];
__device__ h16   g_hb  [(size_t)NTOK*DFFN];
__device__ h16   g_wqh [(size_t)DD*DD];
__device__ h16   g_wkh [(size_t)DD*DD];
__device__ h16   g_wvh [(size_t)DD*DD];
__device__ h16   g_woh [(size_t)DD*DD];
__device__ h16   g_w1h [(size_t)DFFN*DD];
__device__ h16   g_w2h [(size_t)DD*DFFN];

// ---------------------------------------------------------------------------
// PTX helpers (cp.async + mma.sync + ldmatrix + ex2)
// ---------------------------------------------------------------------------
__device__ __forceinline__ uint32_t smem_u32(const void* p) {
    uint32_t a;
    asm("{ .reg .u64 t; cvta.to.shared.u64 t, %1; cvt.u32.u64 %0, t; }"
        : "=r"(a) : "l"(p));
    return a;
}
__device__ __forceinline__ void cp16(uint32_t d, const void* s) {
    asm volatile("cp.async.cg.shared.global [%0], [%1], 16;\n" :: "r"(d), "l"(s));
}
__device__ __forceinline__ void cp_commit() { asm volatile("cp.async.commit_group;\n" ::); }
template<int N> __device__ __forceinline__ void cp_wait() {
    asm volatile("cp.async.wait_group %0;\n" :: "n"(N));
}

__device__ __forceinline__ void mma16816(float* c, const uint32_t* a, const uint32_t* b) {
    asm volatile(
        "mma.sync.aligned.m16n8k16.row.col.f32.f16.f16.f32 "
        "{%0,%1,%2,%3}, {%4,%5,%6,%7}, {%8,%9}, {%0,%1,%2,%3};"
        : "+f"(c[0]), "+f"(c[1]), "+f"(c[2]), "+f"(c[3])
        : "r"(a[0]), "r"(a[1]), "r"(a[2]), "r"(a[3]), "r"(b[0]), "r"(b[1]));
}
__device__ __forceinline__ void ldsm4(uint32_t* r, uint32_t addr) {
    asm volatile("ldmatrix.sync.aligned.m8n8.x4.shared.b16 {%0,%1,%2,%3}, [%4];"
        : "=r"(r[0]), "=r"(r[1]), "=r"(r[2]), "=r"(r[3]) : "r"(addr));
}
__device__ __forceinline__ void ldsm4t(uint32_t* r, uint32_t addr) {
    asm volatile("ldmatrix.sync.aligned.m8n8.x4.trans.shared.b16 {%0,%1,%2,%3}, [%4];"
        : "=r"(r[0]), "=r"(r[1]), "=r"(r[2]), "=r"(r[3]) : "r"(addr));
}
__device__ __forceinline__ uint32_t packh(float lo, float hi) {
    __half2 t = __floats2half2_rn(lo, hi);
    return *(uint32_t*)&t;
}
__device__ __forceinline__ float ex2(float x) {
    float y;
    asm("ex2.approx.ftz.f32 %0, %1;" : "=f"(y) : "f"(x));
    return y;
}

// ---------------------------------------------------------------------------
// Fused convert of all 6 weight matrices fp32 -> fp16, one launch.
// ---------------------------------------------------------------------------
#define CVT_Q (DD*DD/4)        // 262144 (= 2^18)
#define CVT_F (DFFN*DD/4)      // 1048576
#define CVT_TOTAL (4*CVT_Q + 2*CVT_F)   // 3145728

__global__ __launch_bounds__(256) void cvt_all(
    const float* __restrict__ wq, const float* __restrict__ wk,
    const float* __restrict__ wv, const float* __restrict__ wo,
    const float* __restrict__ w1, const float* __restrict__ w2,
    h16* __restrict__ oq, h16* __restrict__ ok, h16* __restrict__ ov,
    h16* __restrict__ oo, h16* __restrict__ o1, h16* __restrict__ o2)
{
    int i = blockIdx.x * 256 + threadIdx.x;
    if (i >= CVT_TOTAL) return;
    const float* src; h16* dst; int off;
    if (i < 4*CVT_Q) {
        int w = i >> 18; off = i & (CVT_Q - 1);
        src = (w==0) ? wq : (w==1) ? wk : (w==2) ? wv : wo;
        dst = (w==0) ? oq : (w==1) ? ok : (w==2) ? ov : oo;
    } else if (i < 4*CVT_Q + CVT_F) {
        src = w1; dst = o1; off = i - 4*CVT_Q;
    } else {
        src = w2; dst = o2; off = i - 4*CVT_Q - CVT_F;
    }
    float4 v = ((const float4*)src)[off];
    ((__half2*)dst)[off*2]   = __floats2half2_rn(v.x, v.y);
    ((__half2*)dst)[off*2+1] = __floats2half2_rn(v.z, v.w);
}

// ---------------------------------------------------------------------------
// LayerNorm -> fp16, warp-per-row. 8 rows per 256-thread CTA, no barriers.
// torch semantics: alpha * (x - mean) / (sqrt(var_unbiased) + eps) + bias
// ---------------------------------------------------------------------------
__global__ __launch_bounds__(256) void layernorm_k(
    const float* __restrict__ x, const float* __restrict__ alpha,
    const float* __restrict__ beta, h16* __restrict__ oh)
{
    int row = blockIdx.x * 8 + (threadIdx.x >> 5);
    int l = threadIdx.x & 31;
    const float4* xr = (const float4*)(x + (size_t)row * DD);

    float4 v[8];
    float s = 0.f, s2 = 0.f;
    #pragma unroll
    for (int j = 0; j < 8; j++) {
        v[j] = xr[l + j * 32];
        s  += v[j].x + v[j].y + v[j].z + v[j].w;
        s2 += v[j].x*v[j].x + v[j].y*v[j].y + v[j].z*v[j].z + v[j].w*v[j].w;
    }
    #pragma unroll
    for (int o = 16; o > 0; o >>= 1) {
        s  += __shfl_xor_sync(0xffffffffu, s,  o);
        s2 += __shfl_xor_sync(0xffffffffu, s2, o);
    }
    float mean = s * (1.0f / (float)DD);
    float var  = (s2 - (float)DD * mean * mean) * (1.0f / (float)(DD - 1));
    var = fmaxf(var, 0.0f);
    float inv = 1.0f / (sqrtf(var) + LN_EPS);

    const float4* ap = (const float4*)alpha;
    const float4* bp = (const float4*)beta;
    __half2* op = (__half2*)(oh + (size_t)row * DD);
    #pragma unroll
    for (int j = 0; j < 8; j++) {
        int idx = l + j * 32;
        float4 a = ap[idx], bb = bp[idx];
        float o0 = a.x * (v[j].x - mean) * inv + bb.x;
        float o1 = a.y * (v[j].y - mean) * inv + bb.y;
        float o2 = a.z * (v[j].z - mean) * inv + bb.z;
        float o3 = a.w * (v[j].w - mean) * inv + bb.w;
        op[idx * 2]     = __floats2half2_rn(o0, o1);
        op[idx * 2 + 1] = __floats2half2_rn(o2, o3);
    }
}

// ---------------------------------------------------------------------------
// GEMM tiling: 128x128 tile, BK=32, 256 threads (8 warps 4x2; 32x64/warp),
// single fp16 product, 4-stage cp.async pipeline (2 in flight), ONE sync
// per chunk. Smem 81920 B -> 2 CTAs/SM (163.8 KB of 228 KB).
// ---------------------------------------------------------------------------
#define BK 32
#define LDSX 40                       // padded row stride in h16 elems (80B)
#define MATB (128 * LDSX * 2)         // 10240 B per matrix tile
#define STAGE (2 * MATB)              // A, B
#define NSTG 4
#define GEMM_SMEM (NSTG * STAGE)      // 81920 B

__device__ __forceinline__ uint32_t a_ldsm_off(int lane) {
    int r = ((lane >> 3) & 1) * 8 + (lane & 7);
    int c = (lane >> 4) * 8;
    return (uint32_t)(r * LDSX + c) * 2;
}
__device__ __forceinline__ uint32_t b_ldsm_off(int lane) {
    int r = (lane >> 4) * 8 + (lane & 7);
    int c = ((lane >> 3) & 1) * 8;
    return (uint32_t)(r * LDSX + c) * 2;
}

template<bool BIAS, bool RELU, bool RES, bool OUTH>
__device__ __forceinline__ void gemm_body(
    const h16* __restrict__ A, const h16* __restrict__ B,
    const float* __restrict__ bias, const float* __restrict__ res,
    float* __restrict__ Cf, h16* __restrict__ Ch,
    int m0, int n0, int N, int K, uint32_t sbase)
{
    int tid = threadIdx.x, lane = tid & 31, wid = tid >> 5;
    int wm = wid & 3, wn = wid >> 2;
    int lr = lane >> 2, lk2 = (lane & 3) * 2;
    uint32_t aoff = a_ldsm_off(lane) + (uint32_t)(wm * 32) * (LDSX * 2);
    uint32_t boff = b_ldsm_off(lane) + (uint32_t)(wn * 64) * (LDSX * 2);

    float acc[2][8][4];
    #pragma unroll
    for (int a = 0; a < 2; a++)
        #pragma unroll
        for (int b = 0; b < 8; b++)
            #pragma unroll
            for (int c = 0; c < 4; c++) acc[a][b][c] = 0.f;

    const int NC = K / BK;

    auto load_chunk = [&](int c, int buf) {
        int kc = c * BK;
        uint32_t base = sbase + buf * STAGE;
        #pragma unroll
        for (int T = 0; T < 2; T++) {
            const h16* src = (T == 0) ? A : B;
            int r0 = (T == 0) ? m0 : n0;
            uint32_t mb = base + T * MATB;
            int row = tid >> 1, c16 = tid & 1;
            cp16(mb + row * (LDSX * 2) + c16 * 32,
                 src + (size_t)(r0 + row) * K + kc + c16 * 16);
            cp16(mb + row * (LDSX * 2) + c16 * 32 + 16,
                 src + (size_t)(r0 + row) * K + kc + c16 * 16 + 8);
        }
        cp_commit();
    };

    load_chunk(0, 0);
    load_chunk(1, 1);
    load_chunk(2, 2);

    for (int c = 0; c < NC; c++) {
        // chunk c must be complete: keep at most 2 younger groups in flight
        if (c + 3 < NC) cp_wait<2>();
        else if (c + 2 < NC) cp_wait<1>();
        else cp_wait<0>();
        __syncthreads();
        // Prefetch c+3 into slot (c+3)%4 == (c-1)%4; readers of that slot
        // (iter c-1) all passed the sync above.
        if (c + 3 < NC) load_chunk(c + 3, (c + 3) % NSTG);

        uint32_t stg = sbase + (c % NSTG) * STAGE;
        uint32_t sA = stg + aoff;
        uint32_t sB = stg + MATB + boff;

        #pragma unroll
        for (int ks = 0; ks < 2; ks++) {
            uint32_t ah[2][4];
            #pragma unroll
            for (int mf = 0; mf < 2; mf++)
                ldsm4(ah[mf], sA + (uint32_t)(mf * 16) * (LDSX * 2) + ks * 32);
            #pragma unroll
            for (int nf2 = 0; nf2 < 4; nf2++) {
                uint32_t bh[4];
                ldsm4(bh, sB + (uint32_t)(nf2 * 16) * (LDSX * 2) + ks * 32);
                #pragma unroll
                for (int mf = 0; mf < 2; mf++) {
                    mma16816(acc[mf][2*nf2],     ah[mf], bh);
                    mma16816(acc[mf][2*nf2 + 1], ah[mf], bh + 2);
                }
            }
        }
    }

    // epilogue
    #pragma unroll
    for (int mf = 0; mf < 2; mf++) {
        int r0 = m0 + wm * 32 + mf * 16 + lr;
        #pragma unroll
        for (int nf = 0; nf < 8; nf++) {
            int col = n0 + wn * 64 + nf * 8 + lk2;
            float* cc = acc[mf][nf];
            float v00 = cc[0], v01 = cc[1], v10 = cc[2], v11 = cc[3];
            if (BIAS) {
                float b0 = __ldg(bias + col), b1 = __ldg(bias + col + 1);
                v00 += b0; v01 += b1; v10 += b0; v11 += b1;
            }
            if (RELU) {
                v00 = fmaxf(v00, 0.f); v01 = fmaxf(v01, 0.f);
                v10 = fmaxf(v10, 0.f); v11 = fmaxf(v11, 0.f);
            }
            if (RES) {
                float2 ra = *(const float2*)(res + (size_t)r0 * N + col);
                float2 rb = *(const float2*)(res + (size_t)(r0 + 8) * N + col);
                v00 += ra.x; v01 += ra.y; v10 += rb.x; v11 += rb.y;
            }
            if (OUTH) {
                *(__half2*)(Ch + (size_t)r0 * N + col)       = __floats2half2_rn(v00, v01);
                *(__half2*)(Ch + (size_t)(r0 + 8) * N + col) = __floats2half2_rn(v10, v11);
            } else {
                *(float2*)(Cf + (size_t)r0 * N + col)       = make_float2(v00, v01);
                *(float2*)(Cf + (size_t)(r0 + 8) * N + col) = make_float2(v10, v11);
            }
        }
    }
}

template<bool BIAS, bool RELU, bool RES, bool OUTH>
__global__ __launch_bounds__(256, 2) void gemm_h(
    const h16* __restrict__ A, const h16* __restrict__ B,
    const float* __restrict__ bias, const float* __restrict__ res,
    float* __restrict__ Cf, h16* __restrict__ Ch, int N, int K)
{
    extern __shared__ char sm_raw[];
    gemm_body<BIAS, RELU, RES, OUTH>(
        A, B, bias, res, Cf, Ch,
        blockIdx.y * 128, blockIdx.x * 128, N, K, smem_u32(sm_raw));
}

// Fused QKV: grid.x = 24; which = bx>>3 selects weight/output.
__global__ __launch_bounds__(256, 2) void gemm_qkv(
    const h16* __restrict__ A,
    const h16* __restrict__ B0, const h16* __restrict__ B1,
    const h16* __restrict__ B2,
    h16* __restrict__ C0, h16* __restrict__ C1, h16* __restrict__ C2)
{
    extern __shared__ char sm_raw[];
    int which = blockIdx.x >> 3;
    const h16* Bw = (which == 0) ? B0 : (which == 1) ? B1 : B2;
    h16* Cw = (which == 0) ? C0 : (which == 1) ? C1 : C2;
    gemm_body<false, false, false, true>(
        A, Bw, nullptr, nullptr, nullptr, Cw,
        blockIdx.y * 128, (blockIdx.x & 7) * 128, DD, DD, smem_u32(sm_raw));
}

// ---------------------------------------------------------------------------
// Flash attention (fp16 mma.sync): one CTA per (b, h, 128-query tile).
// 8 warps x 16 Q rows. K/V chunks of 64 keys, 4-stage cp.async pipeline
// (2 in flight). Base-2 online softmax with Q-folded scale, raw ex2,
// warp-uniform rescale skip.
// ---------------------------------------------------------------------------
#define ANSTG 4
#define AKST 72                       // smem row stride in h16 (144 B)
#define AKBUF (64 * AKST * 2)         // 9216 B per K (or V) stage
#define AVS_OFF (ANSTG * AKBUF)       // 36864
#define AMSK_OFF (2 * ANSTG * AKBUF)  // 73728
#define ATTN_SMEM (AMSK_OFF + ANSTG * 64 * 4)   // 74752 B

#define QSCALE 0.18033688011112042f   // 0.125 * log2(e)

__global__ __launch_bounds__(256, 2) void fattn_k(
    const h16* __restrict__ qg, const h16* __restrict__ kg,
    const h16* __restrict__ vg, const int* __restrict__ mask,
    h16* __restrict__ avo)
{
    extern __shared__ char sm_raw[];
    uint32_t sbase = smem_u32(sm_raw);
    int* msk_s = (int*)(sm_raw + AMSK_OFF);

    int t = threadIdx.x, lane = t & 31, w = t >> 5;
    int h = blockIdx.y & (HH - 1), b = blockIdx.y >> 4;
    size_t base = (size_t)b * SS * DD + h * DKK;
    int q0 = blockIdx.x * 128 + w * 16;
    int lr = lane >> 2, q4 = lane & 3;
    int l7 = lane & 7, lg8 = (lane >> 3) & 1, lg16 = (lane >> 4) & 1;

    const __half2 qs2 = __float2half2_rn(QSCALE);
    uint32_t qf[4][4];
    #pragma unroll
    for (int ks = 0; ks < 4; ks++) {
        int col = ks * 16 + q4 * 2;
        uint32_t r0 = *(const uint32_t*)(qg + base + (size_t)(q0 + lr) * DD + col);
        uint32_t r1 = *(const uint32_t*)(qg + base + (size_t)(q0 + lr + 8) * DD + col);
        uint32_t r2 = *(const uint32_t*)(qg + base + (size_t)(q0 + lr) * DD + col + 8);
        uint32_t r3 = *(const uint32_t*)(qg + base + (size_t)(q0 + lr + 8) * DD + col + 8);
        __half2 h0 = __hmul2(*(__half2*)&r0, qs2);
        __half2 h1 = __hmul2(*(__half2*)&r1, qs2);
        __half2 h2 = __hmul2(*(__half2*)&r2, qs2);
        __half2 h3 = __hmul2(*(__half2*)&r3, qs2);
        qf[ks][0] = *(uint32_t*)&h0;
        qf[ks][1] = *(uint32_t*)&h1;
        qf[ks][2] = *(uint32_t*)&h2;
        qf[ks][3] = *(uint32_t*)&h3;
    }

    float vacc[8][4];
    #pragma unroll
    for (int nf = 0; nf < 8; nf++)
        #pragma unroll
        for (int c = 0; c < 4; c++) vacc[nf][c] = 0.f;
    float m0 = -1e30f, m1 = -1e30f, l0 = 0.f, l1 = 0.f;

    const int NC = SS / 64;

    auto load_chunk = [&](int c, int buf) {
        int key0 = c * 64;
        uint32_t kbAddr = sbase + buf * AKBUF;
        uint32_t vbAddr = sbase + AVS_OFF + buf * AKBUF;
        #pragma unroll
        for (int i = 0; i < 2; i++) {
            int idx = t * 2 + i;
            int row = idx >> 3, seg = idx & 7;
            cp16(kbAddr + row * (AKST * 2) + seg * 16,
                 kg + base + (size_t)(key0 + row) * DD + seg * 8);
            cp16(vbAddr + row * (AKST * 2) + seg * 16,
                 vg + base + (size_t)(key0 + row) * DD + seg * 8);
        }
        if (t < 16)
            cp16(sbase + AMSK_OFF + buf * 256 + t * 16,
                 mask + b * SS + key0 + t * 4);
        cp_commit();
    };

    load_chunk(0, 0);
    load_chunk(1, 1);
    load_chunk(2, 2);

    for (int c = 0; c < NC; c++) {
        if (c + 3 < NC) cp_wait<2>();
        else if (c + 2 < NC) cp_wait<1>();
        else cp_wait<0>();
        __syncthreads();
        // Prefetch c+3 into slot (c+3)%4 == (c-1)%4; readers passed the sync.
        if (c + 3 < NC) load_chunk(c + 3, (c + 3) % ANSTG);
        int buf = c % ANSTG;

        float sacc[8][4];
        #pragma unroll
        for (int nf = 0; nf < 8; nf++)
            #pragma unroll
            for (int cc = 0; cc < 4; cc++) sacc[nf][cc] = 0.f;

        uint32_t ksb = sbase + buf * AKBUF;
        #pragma unroll
        for (int ks = 0; ks < 4; ks++) {
            #pragma unroll
            for (int nfp = 0; nfp < 4; nfp++) {
                uint32_t kf[4];
                uint32_t addr = ksb
                    + (uint32_t)(nfp * 16 + lg16 * 8 + l7) * (AKST * 2)
                    + ks * 32 + lg8 * 16;
                ldsm4(kf, addr);
                mma16816(sacc[2*nfp],     qf[ks], kf);
                mma16816(sacc[2*nfp + 1], qf[ks], kf + 2);
            }
        }

        #pragma unroll
        for (int nf = 0; nf < 8; nf++) {
            int col = nf * 8 + q4 * 2;
            int mk0 = msk_s[buf * 64 + col], mk1 = msk_s[buf * 64 + col + 1];
            if (!mk0) { sacc[nf][0] = -3e8f; sacc[nf][2] = -3e8f; }
            if (!mk1) { sacc[nf][1] = -3e8f; sacc[nf][3] = -3e8f; }
        }

        float cm0 = -1e30f, cm1 = -1e30f;
        #pragma unroll
        for (int nf = 0; nf < 8; nf++) {
            cm0 = fmaxf(cm0, fmaxf(sacc[nf][0], sacc[nf][1]));
            cm1 = fmaxf(cm1, fmaxf(sacc[nf][2], sacc[nf][3]));
        }
        cm0 = fmaxf(cm0, __shfl_xor_sync(0xffffffffu, cm0, 1));
        cm0 = fmaxf(cm0, __shfl_xor_sync(0xffffffffu, cm0, 2));
        cm1 = fmaxf(cm1, __shfl_xor_sync(0xffffffffu, cm1, 1));
        cm1 = fmaxf(cm1, __shfl_xor_sync(0xffffffffu, cm1, 2));
        float nm0 = fmaxf(m0, cm0), nm1 = fmaxf(m1, cm1);

        bool stable = (nm0 == m0) && (nm1 == m1);
        if (!__all_sync(0xffffffffu, stable)) {
            float sc0 = ex2(m0 - nm0), sc1 = ex2(m1 - nm1);
            l0 *= sc0; l1 *= sc1;
            #pragma unroll
            for (int nf = 0; nf < 8; nf++) {
                vacc[nf][0] *= sc0; vacc[nf][1] *= sc0;
                vacc[nf][2] *= sc1; vacc[nf][3] *= sc1;
            }
            m0 = nm0; m1 = nm1;
        }

        #pragma unroll
        for (int nf = 0; nf < 8; nf++) {
            float p0 = ex2(sacc[nf][0] - m0);
            float p1 = ex2(sacc[nf][1] - m0);
            float p2 = ex2(sacc[nf][2] - m1);
            float p3 = ex2(sacc[nf][3] - m1);
            sacc[nf][0] = p0; sacc[nf][1] = p1;
            sacc[nf][2] = p2; sacc[nf][3] = p3;
            l0 += p0 + p1; l1 += p2 + p3;
        }

        uint32_t pf[4][4];
        #pragma unroll
        for (int ks = 0; ks < 4; ks++) {
            pf[ks][0] = packh(sacc[2*ks][0],     sacc[2*ks][1]);
            pf[ks][1] = packh(sacc[2*ks][2],     sacc[2*ks][3]);
            pf[ks][2] = packh(sacc[2*ks + 1][0], sacc[2*ks + 1][1]);
            pf[ks][3] = packh(sacc[2*ks + 1][2], sacc[2*ks + 1][3]);
        }

        uint32_t vsb = sbase + AVS_OFF + buf * AKBUF;
        #pragma unroll
        for (int nfp = 0; nfp < 4; nfp++) {
            #pragma unroll
            for (int ks = 0; ks < 4; ks++) {
                uint32_t vf[4];
                uint32_t addr = vsb
                    + (uint32_t)(ks * 16 + lg8 * 8 + l7) * (AKST * 2)
                    + nfp * 32 + lg16 * 16;
                ldsm4t(vf, addr);
                mma16816(vacc[2*nfp],     pf[ks], vf);
                mma16816(vacc[2*nfp + 1], pf[ks], vf + 2);
            }
        }
    }

    l0 += __shfl_xor_sync(0xffffffffu, l0, 1);
    l0 += __shfl_xor_sync(0xffffffffu, l0, 2);
    l1 += __shfl_xor_sync(0xffffffffu, l1, 1);
    l1 += __shfl_xor_sync(0xffffffffu, l1, 2);
    float r0 = 1.0f / l0, r1 = 1.0f / l1;

    #pragma unroll
    for (int nf = 0; nf < 8; nf++) {
        int col = nf * 8 + q4 * 2;
        size_t o0 = base + (size_t)(q0 + lr) * DD + col;
        size_t o1 = base + (size_t)(q0 + lr + 8) * DD + col;
        *(__half2*)(avo + o0) = __floats2half2_rn(vacc[nf][0] * r0, vacc[nf][1] * r0);
        *(__half2*)(avo + o1) = __floats2half2_rn(vacc[nf][2] * r1, vacc[nf][3] * r1);
    }
}

// ---------------------------------------------------------------------------
// Driver
// ---------------------------------------------------------------------------
extern "C" void kernel_launch(void* const* d_in, const int* in_sizes, int n_in,
                              void* d_out, int out_size)
{
    const float* x      = (const float*)d_in[0];
    const int*   mask   = (const int*)  d_in[1];
    const float* wq     = (const float*)d_in[2];
    const float* wk     = (const float*)d_in[3];
    const float* wv     = (const float*)d_in[4];
    const float* wo     = (const float*)d_in[5];
    const float* w1     = (const float*)d_in[6];
    const float* b1     = (const float*)d_in[7];
    const float* w2     = (const float*)d_in[8];
    const float* b2     = (const float*)d_in[9];
    const float* alpha1 = (const float*)d_in[10];
    const float* bias1  = (const float*)d_in[11];
    const float* alpha2 = (const float*)d_in[12];
    const float* bias2  = (const float*)d_in[13];
    float* out = (float*)d_out;

    h16 *xn, *qb, *kb, *vb, *av, *xn2, *hb;
    h16 *wqh, *wkh, *wvh, *woh, *w1h, *w2h;
    float *x1;
    cudaGetSymbolAddress((void**)&xn,   g_xn);
    cudaGetSymbolAddress((void**)&qb,   g_qb);   cudaGetSymbolAddress((void**)&kb,   g_kb);
    cudaGetSymbolAddress((void**)&vb,   g_vb);
    cudaGetSymbolAddress((void**)&av,   g_av);
    cudaGetSymbolAddress((void**)&x1,   g_x1);
    cudaGetSymbolAddress((void**)&xn2,  g_xn2);
    cudaGetSymbolAddress((void**)&hb,   g_hb);
    cudaGetSymbolAddress((void**)&wqh,  g_wqh);
    cudaGetSymbolAddress((void**)&wkh,  g_wkh);
    cudaGetSymbolAddress((void**)&wvh,  g_wvh);
    cudaGetSymbolAddress((void**)&woh,  g_woh);
    cudaGetSymbolAddress((void**)&w1h,  g_w1h);
    cudaGetSymbolAddress((void**)&w2h,  g_w2h);

    cudaFuncSetAttribute(gemm_h<false,false,true,false>,
                         cudaFuncAttributeMaxDynamicSharedMemorySize, GEMM_SMEM);
    cudaFuncSetAttribute(gemm_h<true,true,false,true>,
                         cudaFuncAttributeMaxDynamicSharedMemorySize, GEMM_SMEM);
    cudaFuncSetAttribute(gemm_h<true,false,true,false>,
                         cudaFuncAttributeMaxDynamicSharedMemorySize, GEMM_SMEM);
    cudaFuncSetAttribute(gemm_qkv,
                         cudaFuncAttributeMaxDynamicSharedMemorySize, GEMM_SMEM);
    cudaFuncSetAttribute(fattn_k,
                         cudaFuncAttributeMaxDynamicSharedMemorySize, ATTN_SMEM);

    // 0. all weights -> fp16, single launch
    cvt_all<<<(CVT_TOTAL + 255)/256, 256>>>(
        wq, wk, wv, wo, w1, w2, wqh, wkh, wvh, woh, w1h, w2h);

    // 1. LN1 -> fp16 (warp-per-row)
    layernorm_k<<<NTOK / 8, 256>>>(x, alpha1, bias1, xn);

    // 2. fused Q/K/V projections (fp16)
    dim3 gQKV(3 * (DD / 128), NTOK / 128);  // (24, 32)
    gemm_qkv<<<gQKV, 256, GEMM_SMEM>>>(xn, wqh, wkh, wvh, qb, kb, vb);

    // 3. flash attention -> fp16
    dim3 gAttn(SS / 128, BB * HH);          // (16, 32)
    fattn_k<<<gAttn, 256, ATTN_SMEM>>>(qb, kb, vb, mask, av);

    // 4. output projection + residual(x) -> x1 fp32
    dim3 gProj(DD / 128, NTOK / 128);       // (8, 32)
    gemm_h<false,false,true,false><<<gProj, 256, GEMM_SMEM>>>(
        av, woh, nullptr, x, x1, nullptr, DD, DD);

    // 5. LN2 -> fp16 (warp-per-row)
    layernorm_k<<<NTOK / 8, 256>>>(x1, alpha2, bias2, xn2);

    // 6. FFN up: relu(xn2@w1^T + b1) -> fp16
    dim3 gF1(DFFN / 128, NTOK / 128);       // (32, 32)
    gemm_h<true,true,false,true><<<gF1, 256, GEMM_SMEM>>>(
        xn2, w1h, b1, nullptr, nullptr, hb, DFFN, DD);

    // 7. FFN down: h@w2^T + b2 + x1 -> out fp32
    gemm_h<true,false,true,false><<<gProj, 256, GEMM_SMEM>>>(
        hb, w2h, b2, x1, out, nullptr, DD, DFFN);
}